// round 15
// baseline (speedup 1.0000x reference)
#include <cuda_runtime.h>
#include <cuda_fp16.h>
#include <cstdint>

#define NB 131072
#define NC 6
#define TILE 128
#define NT 512
#define CF_K 0.02f
#define GRID_X (256 * NC)

// strides in u32 (half2) units — ≡4 mod 32 class => conflict-free fragments
#define SA1 60     // 120 halves (K padded 100->112)
#define SH1 68     // 136 halves (128 used)
#define SH2 36     // 72 halves (64 used)

// smem byte offsets (two tile-groups for A1/H1/P2)
#define OFF_A1  0                        // 2 x 128 x 60 u32      61440
#define OFF_H1  61440                    // 2 x 128 x 68 u32      69632
#define OFF_BW1 131072                   // 7kk x 16nt x 32 x uint2  28672
#define OFF_BW2 159744                   // 8kk x 8nt  x 32 x uint2  16384
#define OFF_BW3 176128                   // 4kk x 4nt  x 32 x uint2   4096
#define OFF_B1  180224                   // 128 f32
#define OFF_B2  180736                   // 64 f32
#define OFF_B3  180992                   // 32 f32
#define OFF_W4  181120                   // 32 f32
#define OFF_P   181248                   // 2 x 128 x 2 f32  2048
#define SMEM_BYTES 183296

// fp16 copy of res (26 MB) + fragment-ordered weights (288 KB)
__device__ uint32_t g_res_h2[NB * 50];
__device__ uint4    g_wpack[6 * 3072];   // per chamber: 1792 BW1 + 1024 BW2 + 256 BW3 uint4

__device__ __forceinline__ uint32_t pack_h2(float a, float b) {
    __half2 h = __floats2half2_rn(a, b);
    return *(uint32_t*)&h;
}

__device__ __forceinline__ void mma_f16(float* d,
    uint32_t a0, uint32_t a1, uint32_t a2, uint32_t a3,
    uint32_t b0, uint32_t b1)
{
    asm volatile(
        "mma.sync.aligned.m16n8k16.row.col.f32.f16.f16.f32 "
        "{%0,%1,%2,%3}, {%4,%5,%6,%7}, {%8,%9}, {%0,%1,%2,%3};"
        : "+f"(d[0]), "+f"(d[1]), "+f"(d[2]), "+f"(d[3])
        : "r"(a0), "r"(a1), "r"(a2), "r"(a3), "r"(b0), "r"(b1));
}

// sigmoid(x) = 0.5*tanh(x/2) + 0.5   (1 MUFU)
__device__ __forceinline__ float sigm(float x) {
    float t;
    asm("tanh.approx.f32 %0, %1;" : "=f"(t) : "f"(0.5f * x));
    return fmaf(0.5f, t, 0.5f);
}
// silu(x) = 0.5x + 0.5x*tanh(x/2)   (1 MUFU)
__device__ __forceinline__ float silu(float x) {
    float t;
    asm("tanh.approx.f32 %0, %1;" : "=f"(t) : "f"(0.5f * x));
    float hx = 0.5f * x;
    return fmaf(hx, t, hx);
}

#define BAR_GRP(id) asm volatile("bar.sync %0, 128;" :: "r"(id) : "memory")

__global__ __launch_bounds__(512) void conv_kernel(const float* __restrict__ res) {
    int i = blockIdx.x * blockDim.x + threadIdx.x;   // < NB*25
    float4 f = ((const float4*)res)[i];
    uint2 u;
    u.x = pack_h2(f.x, f.y);
    u.y = pack_h2(f.z, f.w);
    ((uint2*)g_res_h2)[i] = u;
}

// one-shot: permute all chambers' weights into per-lane fragment order
__global__ __launch_bounds__(256) void wsetup_kernel(
    const float* __restrict__ W1, const float* __restrict__ W2,
    const float* __restrict__ W3)
{
    const int c = blockIdx.x;
    uint2* dst = (uint2*)(g_wpack + (size_t)c * 3072);

    const float* w1 = W1 + (size_t)c * 100 * 128;
    for (int idx = threadIdx.x; idx < 7 * 16 * 32; idx += 256) {
        int kk = idx >> 9, rem = idx & 511;
        int nt = rem >> 5, ln = rem & 31;
        int gg = ln >> 2, tt = ln & 3;
        int n = nt * 8 + gg, k0 = kk * 16 + 2 * tt;
        float v0 = (k0     < 100) ? w1[k0 * 128 + n]       : 0.0f;
        float v1 = (k0 + 1 < 100) ? w1[(k0 + 1) * 128 + n] : 0.0f;
        float v2 = (k0 + 8 < 100) ? w1[(k0 + 8) * 128 + n] : 0.0f;
        float v3 = (k0 + 9 < 100) ? w1[(k0 + 9) * 128 + n] : 0.0f;
        uint2 u; u.x = pack_h2(v0, v1); u.y = pack_h2(v2, v3);
        dst[idx] = u;
    }
    const float* w2 = W2 + (size_t)c * 128 * 64;
    for (int idx = threadIdx.x; idx < 8 * 8 * 32; idx += 256) {
        int kk = idx >> 8, rem = idx & 255;
        int nt = rem >> 5, ln = rem & 31;
        int gg = ln >> 2, tt = ln & 3;
        int n = nt * 8 + gg, k0 = kk * 16 + 2 * tt;
        uint2 u;
        u.x = pack_h2(w2[k0 * 64 + n],       w2[(k0 + 1) * 64 + n]);
        u.y = pack_h2(w2[(k0 + 8) * 64 + n], w2[(k0 + 9) * 64 + n]);
        dst[3584 + idx] = u;
    }
    const float* w3 = W3 + (size_t)c * 64 * 32;
    for (int idx = threadIdx.x; idx < 4 * 4 * 32; idx += 256) {
        int kk = idx >> 7, rem = idx & 127;
        int nt = rem >> 5, ln = rem & 31;
        int gg = ln >> 2, tt = ln & 3;
        int n = nt * 8 + gg, k0 = kk * 16 + 2 * tt;
        uint2 u;
        u.x = pack_h2(w3[k0 * 32 + n],       w3[(k0 + 1) * 32 + n]);
        u.y = pack_h2(w3[(k0 + 8) * 32 + n], w3[(k0 + 9) * 32 + n]);
        dst[5632 + idx] = u;
    }
}

__global__ __launch_bounds__(NT, 1) void mlp_mma_kernel(
    const float* __restrict__ b1, const float* __restrict__ b2,
    const float* __restrict__ b3, const float* __restrict__ W4,
    const float* __restrict__ b4, float* __restrict__ raw_out)
{
    extern __shared__ char smb[];
    float* b1s = (float*)(smb + OFF_B1);
    float* b2s = (float*)(smb + OFF_B2);
    float* b3s = (float*)(smb + OFF_B3);
    float* W4s = (float*)(smb + OFF_W4);

    const int bid   = blockIdx.x;
    const int c     = bid % NC;
    const int tbase = bid / NC;

    const int tid  = threadIdx.x;
    const int w    = tid >> 5;
    const int lane = tid & 31;
    const int g    = lane >> 2;
    const int tg   = lane & 3;
    const int G    = w >> 3;          // tile-group 0/1
    const int bs   = (w >> 2) & 1;    // 64-row stripe
    const int q    = w & 3;           // N quarter
    const int m0   = bs * 64;
    const int barid = 1 + G * 2 + bs;
    const int sg128 = tid & 127;

    uint32_t* A1g = (uint32_t*)(smb + OFF_A1) + G * (128 * SA1);
    uint32_t* H1g = (uint32_t*)(smb + OFF_H1) + G * (128 * SH1);
    float*    P2g = (float*)(smb + OFF_P) + G * 256;

    // ---- prologue: copy pre-permuted weights (L2-hot) + biases ----
    {
        const uint4* src = g_wpack + (size_t)c * 3072;
        uint4* dst = (uint4*)(smb + OFF_BW1);
        #pragma unroll
        for (int i = 0; i < 6; i++) dst[tid + i * NT] = src[tid + i * NT];
        if (tid < 128) b1s[tid] = b1[c * 128 + tid];
        if (tid < 64)  b2s[tid] = b2[c * 64 + tid];
        if (tid < 32)  b3s[tid] = b3[c * 32 + tid];
        if (tid < 32)  W4s[tid] = W4[c * 32 + tid];
    }
    const float b4c = b4[c];
    __syncthreads();

    const uint2* BW1 = (const uint2*)(smb + OFF_BW1);
    const uint2* BW2 = (const uint2*)(smb + OFF_BW2);

    // L3 B fragments (constant): only warps q<2, nt=2 each
    uint2 bw3[4][2];
    if (q < 2) {
        const uint2* BW3 = (const uint2*)(smb + OFF_BW3);
        #pragma unroll
        for (int kk = 0; kk < 4; kk++) {
            bw3[kk][0] = BW3[kk * 128 + (q * 2 + 0) * 32 + lane];
            bw3[kk][1] = BW3[kk * 128 + (q * 2 + 1) * 32 + lane];
        }
    }

    const int h2b = m0 * SA1;   // H2 overlay base inside this group's A1 stripe

    #pragma unroll
    for (int it = 0; it < 2; it++) {
        const int j = 2 * it + G;
        const size_t row0 = (size_t)(tbase + 256 * j) * TILE;

        // ---- load this stripe's 64 res rows (fp16, pad K to 120) ----
        {
            const uint32_t* rp = g_res_h2 + (row0 + m0) * 50;
            #pragma unroll
            for (int i = 0; i < 30; i++) {
                int idx = sg128 + i * 128;         // 0..3839
                int rr = idx / SA1, k2 = idx - rr * SA1;
                A1g[(m0 + rr) * SA1 + k2] = (k2 < 50) ? rp[rr * 50 + k2] : 0u;
            }
        }
        BAR_GRP(barid);

        // ============ L1: [64x112] @ W1 -> 64x32 (4 nt x 4 mh, 7 kk) ========
        float acc1[4][4][4];
        #pragma unroll
        for (int l = 0; l < 4; l++)
            #pragma unroll
            for (int mh = 0; mh < 4; mh++)
                #pragma unroll
                for (int p = 0; p < 4; p++) acc1[l][mh][p] = 0.0f;

        #pragma unroll
        for (int kk = 0; kk < 7; kk++) {
            const int kc2 = kk * 8;
            uint32_t a[4][4];
            #pragma unroll
            for (int mh = 0; mh < 4; mh++) {
                int rb = m0 + mh * 16;
                a[mh][0] = A1g[(rb + g) * SA1 + kc2 + tg];
                a[mh][1] = A1g[(rb + g + 8) * SA1 + kc2 + tg];
                a[mh][2] = A1g[(rb + g) * SA1 + kc2 + 4 + tg];
                a[mh][3] = A1g[(rb + g + 8) * SA1 + kc2 + 4 + tg];
            }
            const uint2* bp = BW1 + kk * 512 + (q * 4) * 32 + lane;
            #pragma unroll
            for (int l = 0; l < 4; l++) {
                uint2 b = bp[l * 32];
                #pragma unroll
                for (int mh = 0; mh < 4; mh++)
                    mma_f16(acc1[l][mh], a[mh][0], a[mh][1], a[mh][2], a[mh][3], b.x, b.y);
            }
        }
        #pragma unroll
        for (int l = 0; l < 4; l++) {
            int col = (q * 4 + l) * 8 + 2 * tg;
            float ba = b1s[col], bb = b1s[col + 1];
            int p2 = (q * 4 + l) * 4 + tg;
            #pragma unroll
            for (int mh = 0; mh < 4; mh++) {
                int rb = m0 + mh * 16;
                H1g[(rb + g) * SH1 + p2]     = pack_h2(silu(acc1[l][mh][0] + ba), silu(acc1[l][mh][1] + bb));
                H1g[(rb + g + 8) * SH1 + p2] = pack_h2(silu(acc1[l][mh][2] + ba), silu(acc1[l][mh][3] + bb));
            }
        }
        BAR_GRP(barid);

        // ============ L2: [64x128] @ W2 -> 64x16 (2 nt x 4 mh, 8 kk) ========
        float acc2[2][4][4];
        #pragma unroll
        for (int l = 0; l < 2; l++)
            #pragma unroll
            for (int mh = 0; mh < 4; mh++)
                #pragma unroll
                for (int p = 0; p < 4; p++) acc2[l][mh][p] = 0.0f;

        #pragma unroll
        for (int kk = 0; kk < 8; kk++) {
            const int kc2 = kk * 8;
            uint32_t a[4][4];
            #pragma unroll
            for (int mh = 0; mh < 4; mh++) {
                int rb = m0 + mh * 16;
                a[mh][0] = H1g[(rb + g) * SH1 + kc2 + tg];
                a[mh][1] = H1g[(rb + g + 8) * SH1 + kc2 + tg];
                a[mh][2] = H1g[(rb + g) * SH1 + kc2 + 4 + tg];
                a[mh][3] = H1g[(rb + g + 8) * SH1 + kc2 + 4 + tg];
            }
            const uint2* bp = BW2 + kk * 256 + (q * 2) * 32 + lane;
            #pragma unroll
            for (int l = 0; l < 2; l++) {
                uint2 b = bp[l * 32];
                #pragma unroll
                for (int mh = 0; mh < 4; mh++)
                    mma_f16(acc2[l][mh], a[mh][0], a[mh][1], a[mh][2], a[mh][3], b.x, b.y);
            }
        }
        #pragma unroll
        for (int l = 0; l < 2; l++) {
            int col = (q * 2 + l) * 8 + 2 * tg;
            float ba = b2s[col], bb = b2s[col + 1];
            int p2 = (q * 2 + l) * 4 + tg;
            #pragma unroll
            for (int mh = 0; mh < 4; mh++) {
                int r2 = mh * 16;
                A1g[h2b + (r2 + g) * SH2 + p2]       = pack_h2(silu(acc2[l][mh][0] + ba), silu(acc2[l][mh][1] + bb));
                A1g[h2b + (r2 + g + 8) * SH2 + p2]   = pack_h2(silu(acc2[l][mh][2] + ba), silu(acc2[l][mh][3] + bb));
            }
        }
        BAR_GRP(barid);

        // ============ L3: [64x64] @ W3 -> 64x32, warps q<2 (2 nt x 4 mh) ====
        if (q < 2) {
            float acc3[2][4][4];
            #pragma unroll
            for (int l = 0; l < 2; l++)
                #pragma unroll
                for (int mh = 0; mh < 4; mh++)
                    #pragma unroll
                    for (int p = 0; p < 4; p++) acc3[l][mh][p] = 0.0f;

            #pragma unroll
            for (int kk = 0; kk < 4; kk++) {
                const int kc2 = kk * 8;
                uint32_t a[4][4];
                #pragma unroll
                for (int mh = 0; mh < 4; mh++) {
                    int r2 = mh * 16;
                    a[mh][0] = A1g[h2b + (r2 + g) * SH2 + kc2 + tg];
                    a[mh][1] = A1g[h2b + (r2 + g + 8) * SH2 + kc2 + tg];
                    a[mh][2] = A1g[h2b + (r2 + g) * SH2 + kc2 + 4 + tg];
                    a[mh][3] = A1g[h2b + (r2 + g + 8) * SH2 + kc2 + 4 + tg];
                }
                #pragma unroll
                for (int l = 0; l < 2; l++)
                    #pragma unroll
                    for (int mh = 0; mh < 4; mh++)
                        mma_f16(acc3[l][mh], a[mh][0], a[mh][1], a[mh][2], a[mh][3],
                                bw3[kk][l].x, bw3[kk][l].y);
            }

            // ---- epi3: partial dot over this warp's 16 cols ----
            #pragma unroll
            for (int mh = 0; mh < 4; mh++) {
                float s0 = 0.0f, s1 = 0.0f;
                #pragma unroll
                for (int l = 0; l < 2; l++) {
                    int col = (q * 2 + l) * 8 + 2 * tg;
                    float ba = b3s[col], bb = b3s[col + 1];
                    float wa = W4s[col], wb = W4s[col + 1];
                    s0 = fmaf(silu(acc3[l][mh][0] + ba), wa, s0);
                    s0 = fmaf(silu(acc3[l][mh][1] + bb), wb, s0);
                    s1 = fmaf(silu(acc3[l][mh][2] + ba), wa, s1);
                    s1 = fmaf(silu(acc3[l][mh][3] + bb), wb, s1);
                }
                s0 += __shfl_xor_sync(0xffffffff, s0, 1);
                s0 += __shfl_xor_sync(0xffffffff, s0, 2);
                s1 += __shfl_xor_sync(0xffffffff, s1, 1);
                s1 += __shfl_xor_sync(0xffffffff, s1, 2);
                if (tg == 0) {
                    P2g[(m0 + mh * 16 + g) * 2 + q]     = s0;
                    P2g[(m0 + mh * 16 + g + 8) * 2 + q] = s1;
                }
            }
        }
        BAR_GRP(barid);

        if (q >= 2) {
            int row = m0 + (q - 2) * 32 + lane;
            raw_out[(row0 + row) * NC + c] = P2g[row * 2] + P2g[row * 2 + 1] + b4c;
        }
        BAR_GRP(barid);   // stripe drained; A1/P2 reusable next iteration
    }
}

__global__ __launch_bounds__(256) void couple_kernel(
    const float* __restrict__ raw, float* __restrict__ act,
    const float* __restrict__ coupling, const float* __restrict__ decay)
{
    __shared__ float M[NC][NC];
    if (threadIdx.x < NC * NC) {
        int cp = threadIdx.x / NC;
        int cc = threadIdx.x % NC;
        M[cp][cc] = decay[cp] * coupling[cp * NC + cc] * CF_K;
    }
    __syncthreads();

    int r = blockIdx.x * blockDim.x + threadIdx.x;
    if (r >= NB) return;

    float rw[NC], a[NC];
    const float2* rp = (const float2*)(raw + (size_t)r * NC);
    #pragma unroll
    for (int h = 0; h < 3; h++) {
        float2 v = rp[h];
        rw[2 * h] = v.x; rw[2 * h + 1] = v.y;
    }
    #pragma unroll
    for (int c = 0; c < NC; c++) a[c] = sigm(rw[c]);

    #pragma unroll
    for (int it = 0; it < 5; it++) {
        float d[NC];
        #pragma unroll
        for (int c = 0; c < NC; c++) d[c] = 0.0f;
        #pragma unroll
        for (int cp = 0; cp < NC; cp++)
            #pragma unroll
            for (int cc = 0; cc < NC; cc++)
                d[cc] = fmaf(a[cp], M[cp][cc], d[cc]);
        #pragma unroll
        for (int c = 0; c < NC; c++) a[c] = sigm(rw[c] + d[c]);
    }
    float2* ap = (float2*)(act + (size_t)r * NC);
    #pragma unroll
    for (int h = 0; h < 3; h++) {
        float2 v; v.x = a[2 * h]; v.y = a[2 * h + 1];
        ap[h] = v;
    }
}

extern "C" void kernel_launch(void* const* d_in, const int* in_sizes, int n_in,
                              void* d_out, int out_size)
{
    (void)in_sizes; (void)n_in; (void)out_size;
    const float* res      = (const float*)d_in[0];
    const float* W1       = (const float*)d_in[1];
    const float* b1       = (const float*)d_in[2];
    const float* W2       = (const float*)d_in[3];
    const float* b2       = (const float*)d_in[4];
    const float* W3       = (const float*)d_in[5];
    const float* b3       = (const float*)d_in[6];
    const float* W4       = (const float*)d_in[7];
    const float* b4       = (const float*)d_in[8];
    const float* coupling = (const float*)d_in[9];
    const float* decay    = (const float*)d_in[10];

    float* act = (float*)d_out;             // (B, 6)
    float* raw = act + (size_t)NB * NC;     // (B, 6)

    cudaFuncSetAttribute(mlp_mma_kernel, cudaFuncAttributeMaxDynamicSharedMemorySize, SMEM_BYTES);

    conv_kernel<<<NB * 25 / 512, 512>>>(res);
    wsetup_kernel<<<NC, 256>>>(W1, W2, W3);
    mlp_mma_kernel<<<GRID_X, NT, SMEM_BYTES>>>(b1, b2, b3, W4, b4, raw);
    couple_kernel<<<NB / 256, 256>>>(raw, act, coupling, decay);
}

// round 16
// speedup vs baseline: 1.1101x; 1.1101x over previous
#include <cuda_runtime.h>
#include <cuda_fp16.h>
#include <cstdint>

#define NB 131072
#define NC 6
#define TILE 128
#define NT 1024
#define CF_K 0.02f
#define GRID_X (256 * NC)

// strides in u32 (half2) units — ≡4 mod 32 class => conflict-free fragments
#define SA1 60     // 120 halves (K padded 100->112)
#define SH1 68     // 136 halves (128 used)
#define SH2 36     // 72 halves (64 used)

// smem byte offsets (two tile-groups for A1/H1/P4)
#define OFF_A1  0                        // 2 x 128 x 60 u32      61440
#define OFF_H1  61440                    // 2 x 128 x 68 u32      69632
#define OFF_BW1 131072                   // 7kk x 16nt x 32 x uint2  28672
#define OFF_BW2 159744                   // 8kk x 8nt  x 32 x uint2  16384
#define OFF_BW3 176128                   // 4kk x 4nt  x 32 x uint2   4096
#define OFF_B1  180224                   // 128 f32
#define OFF_B2  180736                   // 64 f32
#define OFF_B3  180992                   // 32 f32
#define OFF_W4  181120                   // 32 f32
#define OFF_P   181248                   // 2 x 128 x 4 f32  4096
#define SMEM_BYTES 185344

// fp16 copy of res (26 MB) + fragment-ordered weights (288 KB)
__device__ uint32_t g_res_h2[NB * 50];
__device__ uint4    g_wpack[6 * 3072];   // per chamber: 1792 BW1 + 1024 BW2 + 256 BW3 uint4

__device__ __forceinline__ uint32_t pack_h2(float a, float b) {
    __half2 h = __floats2half2_rn(a, b);
    return *(uint32_t*)&h;
}

__device__ __forceinline__ void mma_f16(float* d,
    uint32_t a0, uint32_t a1, uint32_t a2, uint32_t a3,
    uint32_t b0, uint32_t b1)
{
    asm volatile(
        "mma.sync.aligned.m16n8k16.row.col.f32.f16.f16.f32 "
        "{%0,%1,%2,%3}, {%4,%5,%6,%7}, {%8,%9}, {%0,%1,%2,%3};"
        : "+f"(d[0]), "+f"(d[1]), "+f"(d[2]), "+f"(d[3])
        : "r"(a0), "r"(a1), "r"(a2), "r"(a3), "r"(b0), "r"(b1));
}

// sigmoid(x) = 0.5*tanh(x/2) + 0.5   (1 MUFU)
__device__ __forceinline__ float sigm(float x) {
    float t;
    asm("tanh.approx.f32 %0, %1;" : "=f"(t) : "f"(0.5f * x));
    return fmaf(0.5f, t, 0.5f);
}
// silu(x) = 0.5x + 0.5x*tanh(x/2)   (1 MUFU)
__device__ __forceinline__ float silu(float x) {
    float t;
    asm("tanh.approx.f32 %0, %1;" : "=f"(t) : "f"(0.5f * x));
    float hx = 0.5f * x;
    return fmaf(hx, t, hx);
}

#define BAR_GRP(id) asm volatile("bar.sync %0, 128;" :: "r"(id) : "memory")

__global__ __launch_bounds__(512) void conv_kernel(const float* __restrict__ res) {
    int i = blockIdx.x * blockDim.x + threadIdx.x;   // < NB*25
    float4 f = ((const float4*)res)[i];
    uint2 u;
    u.x = pack_h2(f.x, f.y);
    u.y = pack_h2(f.z, f.w);
    ((uint2*)g_res_h2)[i] = u;
}

// one-shot: permute all chambers' weights into per-lane fragment order
__global__ __launch_bounds__(256) void wsetup_kernel(
    const float* __restrict__ W1, const float* __restrict__ W2,
    const float* __restrict__ W3)
{
    const int c = blockIdx.x;
    uint2* dst = (uint2*)(g_wpack + (size_t)c * 3072);

    const float* w1 = W1 + (size_t)c * 100 * 128;
    for (int idx = threadIdx.x; idx < 7 * 16 * 32; idx += 256) {
        int kk = idx >> 9, rem = idx & 511;
        int nt = rem >> 5, ln = rem & 31;
        int gg = ln >> 2, tt = ln & 3;
        int n = nt * 8 + gg, k0 = kk * 16 + 2 * tt;
        float v0 = (k0     < 100) ? w1[k0 * 128 + n]       : 0.0f;
        float v1 = (k0 + 1 < 100) ? w1[(k0 + 1) * 128 + n] : 0.0f;
        float v2 = (k0 + 8 < 100) ? w1[(k0 + 8) * 128 + n] : 0.0f;
        float v3 = (k0 + 9 < 100) ? w1[(k0 + 9) * 128 + n] : 0.0f;
        uint2 u; u.x = pack_h2(v0, v1); u.y = pack_h2(v2, v3);
        dst[idx] = u;
    }
    const float* w2 = W2 + (size_t)c * 128 * 64;
    for (int idx = threadIdx.x; idx < 8 * 8 * 32; idx += 256) {
        int kk = idx >> 8, rem = idx & 255;
        int nt = rem >> 5, ln = rem & 31;
        int gg = ln >> 2, tt = ln & 3;
        int n = nt * 8 + gg, k0 = kk * 16 + 2 * tt;
        uint2 u;
        u.x = pack_h2(w2[k0 * 64 + n],       w2[(k0 + 1) * 64 + n]);
        u.y = pack_h2(w2[(k0 + 8) * 64 + n], w2[(k0 + 9) * 64 + n]);
        dst[3584 + idx] = u;
    }
    const float* w3 = W3 + (size_t)c * 64 * 32;
    for (int idx = threadIdx.x; idx < 4 * 4 * 32; idx += 256) {
        int kk = idx >> 7, rem = idx & 127;
        int nt = rem >> 5, ln = rem & 31;
        int gg = ln >> 2, tt = ln & 3;
        int n = nt * 8 + gg, k0 = kk * 16 + 2 * tt;
        uint2 u;
        u.x = pack_h2(w3[k0 * 32 + n],       w3[(k0 + 1) * 32 + n]);
        u.y = pack_h2(w3[(k0 + 8) * 32 + n], w3[(k0 + 9) * 32 + n]);
        dst[5632 + idx] = u;
    }
}

__global__ __launch_bounds__(NT, 1) void mlp_mma_kernel(
    const float* __restrict__ b1, const float* __restrict__ b2,
    const float* __restrict__ b3, const float* __restrict__ W4,
    const float* __restrict__ b4, float* __restrict__ raw_out)
{
    extern __shared__ char smb[];
    float* b1s = (float*)(smb + OFF_B1);
    float* b2s = (float*)(smb + OFF_B2);
    float* b3s = (float*)(smb + OFF_B3);
    float* W4s = (float*)(smb + OFF_W4);

    const int bid   = blockIdx.x;
    const int c     = bid % NC;
    const int tbase = bid / NC;

    const int tid  = threadIdx.x;
    const int w    = tid >> 5;
    const int lane = tid & 31;
    const int g    = lane >> 2;
    const int tg   = lane & 3;
    const int G    = w >> 4;          // tile-group 0/1
    const int bs   = (w >> 2) & 3;    // big-stripe (32 rows)
    const int q    = w & 3;           // N quarter
    const int m0   = bs * 32;
    const int barid = 1 + G * 4 + bs;
    const int sg128 = tid & 127;

    uint32_t* A1g = (uint32_t*)(smb + OFF_A1) + G * (128 * SA1);
    uint32_t* H1g = (uint32_t*)(smb + OFF_H1) + G * (128 * SH1);
    float*    P4g = (float*)(smb + OFF_P) + G * 512;

    // ---- prologue: copy pre-permuted weights (L2-hot) + biases ----
    {
        const uint4* src = g_wpack + (size_t)c * 3072;
        uint4* dst = (uint4*)(smb + OFF_BW1);
        #pragma unroll
        for (int i = 0; i < 3; i++) dst[tid + i * NT] = src[tid + i * NT];
        if (tid < 128) b1s[tid] = b1[c * 128 + tid];
        if (tid < 64)  b2s[tid] = b2[c * 64 + tid];
        if (tid < 32)  b3s[tid] = b3[c * 32 + tid];
        if (tid < 32)  W4s[tid] = W4[c * 32 + tid];
    }
    const float b4c = b4[c];
    __syncthreads();

    const uint2* BW1 = (const uint2*)(smb + OFF_BW1);
    const uint2* BW2 = (const uint2*)(smb + OFF_BW2);

    // hoist L3 B fragments (constant): 4 kk, this warp's nt = q
    uint2 bw3[4];
    {
        const uint2* BW3 = (const uint2*)(smb + OFF_BW3);
        #pragma unroll
        for (int kk = 0; kk < 4; kk++) bw3[kk] = BW3[kk * 128 + q * 32 + lane];
    }

    const int h2b = m0 * SA1;   // H2 overlay base inside this group/stripe of A1

    #pragma unroll
    for (int it = 0; it < 2; it++) {
        const int j = 2 * it + G;
        const size_t row0 = (size_t)(tbase + 256 * j) * TILE;

        // ---- load this big-stripe's 32 res rows (fp16, pad K to 120) ----
        {
            const uint32_t* rp = g_res_h2 + (row0 + m0) * 50;
            #pragma unroll
            for (int i = 0; i < 15; i++) {
                int idx = sg128 + i * 128;         // 0..1919
                int rr = idx / SA1, k2 = idx - rr * SA1;
                A1g[(m0 + rr) * SA1 + k2] = (k2 < 50) ? rp[rr * 50 + k2] : 0u;
            }
        }
        BAR_GRP(barid);

        // ============ L1: [32x112] @ W1 -> 32x32 (4 nt x 2 mh, 7 kk) ========
        float acc1[4][2][4];
        #pragma unroll
        for (int l = 0; l < 4; l++)
            #pragma unroll
            for (int mh = 0; mh < 2; mh++)
                #pragma unroll
                for (int p = 0; p < 4; p++) acc1[l][mh][p] = 0.0f;

        #pragma unroll
        for (int kk = 0; kk < 7; kk++) {
            const int kc2 = kk * 8;
            uint32_t a[2][4];
            #pragma unroll
            for (int mh = 0; mh < 2; mh++) {
                int rb = m0 + mh * 16;
                a[mh][0] = A1g[(rb + g) * SA1 + kc2 + tg];
                a[mh][1] = A1g[(rb + g + 8) * SA1 + kc2 + tg];
                a[mh][2] = A1g[(rb + g) * SA1 + kc2 + 4 + tg];
                a[mh][3] = A1g[(rb + g + 8) * SA1 + kc2 + 4 + tg];
            }
            const uint2* bp = BW1 + kk * 512 + (q * 4) * 32 + lane;
            #pragma unroll
            for (int l = 0; l < 4; l++) {
                uint2 b = bp[l * 32];
                mma_f16(acc1[l][0], a[0][0], a[0][1], a[0][2], a[0][3], b.x, b.y);
                mma_f16(acc1[l][1], a[1][0], a[1][1], a[1][2], a[1][3], b.x, b.y);
            }
        }
        #pragma unroll
        for (int l = 0; l < 4; l++) {
            int col = (q * 4 + l) * 8 + 2 * tg;
            float ba = b1s[col], bb = b1s[col + 1];
            int p2 = (q * 4 + l) * 4 + tg;
            #pragma unroll
            for (int mh = 0; mh < 2; mh++) {
                int rb = m0 + mh * 16;
                H1g[(rb + g) * SH1 + p2]     = pack_h2(silu(acc1[l][mh][0] + ba), silu(acc1[l][mh][1] + bb));
                H1g[(rb + g + 8) * SH1 + p2] = pack_h2(silu(acc1[l][mh][2] + ba), silu(acc1[l][mh][3] + bb));
            }
        }
        BAR_GRP(barid);

        // ============ L2: [32x128] @ W2 -> 32x16 (2 nt x 2 mh, 8 kk) ========
        float acc2[2][2][4];
        #pragma unroll
        for (int l = 0; l < 2; l++)
            #pragma unroll
            for (int mh = 0; mh < 2; mh++)
                #pragma unroll
                for (int p = 0; p < 4; p++) acc2[l][mh][p] = 0.0f;

        #pragma unroll
        for (int kk = 0; kk < 8; kk++) {
            const int kc2 = kk * 8;
            uint32_t a[2][4];
            #pragma unroll
            for (int mh = 0; mh < 2; mh++) {
                int rb = m0 + mh * 16;
                a[mh][0] = H1g[(rb + g) * SH1 + kc2 + tg];
                a[mh][1] = H1g[(rb + g + 8) * SH1 + kc2 + tg];
                a[mh][2] = H1g[(rb + g) * SH1 + kc2 + 4 + tg];
                a[mh][3] = H1g[(rb + g + 8) * SH1 + kc2 + 4 + tg];
            }
            const uint2* bp = BW2 + kk * 256 + (q * 2) * 32 + lane;
            #pragma unroll
            for (int l = 0; l < 2; l++) {
                uint2 b = bp[l * 32];
                mma_f16(acc2[l][0], a[0][0], a[0][1], a[0][2], a[0][3], b.x, b.y);
                mma_f16(acc2[l][1], a[1][0], a[1][1], a[1][2], a[1][3], b.x, b.y);
            }
        }
        #pragma unroll
        for (int l = 0; l < 2; l++) {
            int col = (q * 2 + l) * 8 + 2 * tg;
            float ba = b2s[col], bb = b2s[col + 1];
            int p2 = (q * 2 + l) * 4 + tg;
            #pragma unroll
            for (int mh = 0; mh < 2; mh++) {
                int r2 = mh * 16;
                A1g[h2b + (r2 + g) * SH2 + p2]     = pack_h2(silu(acc2[l][mh][0] + ba), silu(acc2[l][mh][1] + bb));
                A1g[h2b + (r2 + g + 8) * SH2 + p2] = pack_h2(silu(acc2[l][mh][2] + ba), silu(acc2[l][mh][3] + bb));
            }
        }
        BAR_GRP(barid);

        // ============ L3: [32x64] @ W3 -> 32x8 (1 nt x 2 mh, 4 kk) ==========
        float acc3[2][4];
        #pragma unroll
        for (int mh = 0; mh < 2; mh++)
            #pragma unroll
            for (int p = 0; p < 4; p++) acc3[mh][p] = 0.0f;

        #pragma unroll
        for (int kk = 0; kk < 4; kk++) {
            const int kc2 = kk * 8;
            #pragma unroll
            for (int mh = 0; mh < 2; mh++) {
                int r2 = mh * 16;
                uint32_t a0 = A1g[h2b + (r2 + g) * SH2 + kc2 + tg];
                uint32_t a1 = A1g[h2b + (r2 + g + 8) * SH2 + kc2 + tg];
                uint32_t a2 = A1g[h2b + (r2 + g) * SH2 + kc2 + 4 + tg];
                uint32_t a3 = A1g[h2b + (r2 + g + 8) * SH2 + kc2 + 4 + tg];
                mma_f16(acc3[mh], a0, a1, a2, a3, bw3[kk].x, bw3[kk].y);
            }
        }

        // ---- epi3: partial dot over this warp's 8 cols ----
        {
            int col = q * 8 + 2 * tg;
            float ba = b3s[col], bb = b3s[col + 1];
            float wa = W4s[col], wb = W4s[col + 1];
            #pragma unroll
            for (int mh = 0; mh < 2; mh++) {
                float s0 = fmaf(silu(acc3[mh][0] + ba), wa, silu(acc3[mh][1] + bb) * wb);
                float s1 = fmaf(silu(acc3[mh][2] + ba), wa, silu(acc3[mh][3] + bb) * wb);
                s0 += __shfl_xor_sync(0xffffffff, s0, 1);
                s0 += __shfl_xor_sync(0xffffffff, s0, 2);
                s1 += __shfl_xor_sync(0xffffffff, s1, 1);
                s1 += __shfl_xor_sync(0xffffffff, s1, 2);
                if (tg == 0) {
                    P4g[(m0 + mh * 16 + g) * 4 + q]     = s0;
                    P4g[(m0 + mh * 16 + g + 8) * 4 + q] = s1;
                }
            }
        }
        BAR_GRP(barid);

        if (q == 0) {
            float4 p = *(float4*)&P4g[(m0 + lane) * 4];
            raw_out[(row0 + m0 + lane) * NC + c] = p.x + p.y + p.z + p.w + b4c;
        }
        BAR_GRP(barid);   // stripe drained; A1/P4 reusable next iteration
    }
}

__global__ __launch_bounds__(256) void couple_kernel(
    const float* __restrict__ raw, float* __restrict__ act,
    const float* __restrict__ coupling, const float* __restrict__ decay)
{
    __shared__ float M[NC][NC];
    if (threadIdx.x < NC * NC) {
        int cp = threadIdx.x / NC;
        int cc = threadIdx.x % NC;
        M[cp][cc] = decay[cp] * coupling[cp * NC + cc] * CF_K;
    }
    __syncthreads();

    int r = blockIdx.x * blockDim.x + threadIdx.x;
    if (r >= NB) return;

    float rw[NC], a[NC];
    const float2* rp = (const float2*)(raw + (size_t)r * NC);
    #pragma unroll
    for (int h = 0; h < 3; h++) {
        float2 v = rp[h];
        rw[2 * h] = v.x; rw[2 * h + 1] = v.y;
    }
    #pragma unroll
    for (int c = 0; c < NC; c++) a[c] = sigm(rw[c]);

    #pragma unroll
    for (int it = 0; it < 5; it++) {
        float d[NC];
        #pragma unroll
        for (int c = 0; c < NC; c++) d[c] = 0.0f;
        #pragma unroll
        for (int cp = 0; cp < NC; cp++)
            #pragma unroll
            for (int cc = 0; cc < NC; cc++)
                d[cc] = fmaf(a[cp], M[cp][cc], d[cc]);
        #pragma unroll
        for (int c = 0; c < NC; c++) a[c] = sigm(rw[c] + d[c]);
    }
    float2* ap = (float2*)(act + (size_t)r * NC);
    #pragma unroll
    for (int h = 0; h < 3; h++) {
        float2 v; v.x = a[2 * h]; v.y = a[2 * h + 1];
        ap[h] = v;
    }
}

extern "C" void kernel_launch(void* const* d_in, const int* in_sizes, int n_in,
                              void* d_out, int out_size)
{
    (void)in_sizes; (void)n_in; (void)out_size;
    const float* res      = (const float*)d_in[0];
    const float* W1       = (const float*)d_in[1];
    const float* b1       = (const float*)d_in[2];
    const float* W2       = (const float*)d_in[3];
    const float* b2       = (const float*)d_in[4];
    const float* W3       = (const float*)d_in[5];
    const float* b3       = (const float*)d_in[6];
    const float* W4       = (const float*)d_in[7];
    const float* b4       = (const float*)d_in[8];
    const float* coupling = (const float*)d_in[9];
    const float* decay    = (const float*)d_in[10];

    float* act = (float*)d_out;             // (B, 6)
    float* raw = act + (size_t)NB * NC;     // (B, 6)

    cudaFuncSetAttribute(mlp_mma_kernel, cudaFuncAttributeMaxDynamicSharedMemorySize, SMEM_BYTES);

    conv_kernel<<<NB * 25 / 512, 512>>>(res);
    wsetup_kernel<<<NC, 256>>>(W1, W2, W3);
    mlp_mma_kernel<<<GRID_X, NT, SMEM_BYTES>>>(b1, b2, b3, W4, b4, raw);
    couple_kernel<<<NB / 256, 256>>>(raw, act, coupling, decay);
}

// round 17
// speedup vs baseline: 1.1222x; 1.0109x over previous
#include <cuda_runtime.h>
#include <cuda_fp16.h>
#include <cstdint>

#define NB 131072
#define NC 6
#define TILE 128
#define NT 1024
#define CF_K 0.02f
#define GRID_X (256 * NC)

// strides in u32 (half2) units — ≡4 mod 32 class => conflict-free fragments
#define SA1 60     // 120 halves (K padded 100->112)
#define SH1 68     // 136 halves (128 used)
#define SH2 36     // 72 halves (64 used)

// smem byte offsets (two tile-groups for A1/H1/P4)
#define OFF_A1  0                        // 2 x 128 x 60 u32      61440
#define OFF_H1  61440                    // 2 x 128 x 68 u32      69632
#define OFF_BW1 131072                   // 7kk x 16nt x 32 x uint2  28672
#define OFF_BW2 159744                   // 8kk x 8nt  x 32 x uint2  16384
#define OFF_BW3 176128                   // 4kk x 4nt  x 32 x uint2   4096
#define OFF_B1  180224                   // 128 f32
#define OFF_B2  180736                   // 64 f32
#define OFF_B3  180992                   // 32 f32
#define OFF_W4  181120                   // 32 f32
#define OFF_P   181248                   // 2 x 128 x 4 f32  4096
#define SMEM_BYTES 185344

// fp16 copy of res (26 MB) + fragment-ordered weights (288 KB)
__device__ uint32_t g_res_h2[NB * 50];
__device__ uint4    g_wpack[6 * 3072];   // per chamber: 1792 BW1 + 1024 BW2 + 256 BW3 uint4

__device__ __forceinline__ uint32_t pack_h2(float a, float b) {
    __half2 h = __floats2half2_rn(a, b);
    return *(uint32_t*)&h;
}

__device__ __forceinline__ uint32_t s_addr(const void* p) {
    return (uint32_t)__cvta_generic_to_shared(p);
}

__device__ __forceinline__ void ldsm_x4(uint32_t* r, uint32_t addr) {
    asm volatile("ldmatrix.sync.aligned.m8n8.x4.shared.b16 {%0,%1,%2,%3}, [%4];"
        : "=r"(r[0]), "=r"(r[1]), "=r"(r[2]), "=r"(r[3]) : "r"(addr));
}

__device__ __forceinline__ void mma_f16(float* d,
    uint32_t a0, uint32_t a1, uint32_t a2, uint32_t a3,
    uint32_t b0, uint32_t b1)
{
    asm volatile(
        "mma.sync.aligned.m16n8k16.row.col.f32.f16.f16.f32 "
        "{%0,%1,%2,%3}, {%4,%5,%6,%7}, {%8,%9}, {%0,%1,%2,%3};"
        : "+f"(d[0]), "+f"(d[1]), "+f"(d[2]), "+f"(d[3])
        : "r"(a0), "r"(a1), "r"(a2), "r"(a3), "r"(b0), "r"(b1));
}

// sigmoid(x) = 0.5*tanh(x/2) + 0.5   (1 MUFU)
__device__ __forceinline__ float sigm(float x) {
    float t;
    asm("tanh.approx.f32 %0, %1;" : "=f"(t) : "f"(0.5f * x));
    return fmaf(0.5f, t, 0.5f);
}
// fp32 silu (kept for epi3)
__device__ __forceinline__ float silu(float x) {
    float t;
    asm("tanh.approx.f32 %0, %1;" : "=f"(t) : "f"(0.5f * x));
    float hx = 0.5f * x;
    return fmaf(hx, t, hx);
}
// packed half2 silu: silu(x) = 0.5x*(1+tanh(0.5x)); bias-add in fp32, one MUFU for 2 lanes
__device__ __forceinline__ uint32_t silu2(float a, float b) {
    __half2 hx = __floats2half2_rn(0.5f * a, 0.5f * b);
    uint32_t hxu = *(uint32_t*)&hx;
    uint32_t tu;
    asm("tanh.approx.f16x2 %0, %1;" : "=r"(tu) : "r"(hxu));
    __half2 r = __hfma2(hx, *(__half2*)&tu, hx);
    return *(uint32_t*)&r;
}

#define BAR_GRP(id) asm volatile("bar.sync %0, 128;" :: "r"(id) : "memory")

__global__ __launch_bounds__(512) void conv_kernel(const float* __restrict__ res) {
    int i = blockIdx.x * blockDim.x + threadIdx.x;   // < NB*25
    float4 f = ((const float4*)res)[i];
    uint2 u;
    u.x = pack_h2(f.x, f.y);
    u.y = pack_h2(f.z, f.w);
    ((uint2*)g_res_h2)[i] = u;
}

// one-shot: permute all chambers' weights into per-lane fragment order
__global__ __launch_bounds__(256) void wsetup_kernel(
    const float* __restrict__ W1, const float* __restrict__ W2,
    const float* __restrict__ W3)
{
    const int c = blockIdx.x;
    uint2* dst = (uint2*)(g_wpack + (size_t)c * 3072);

    const float* w1 = W1 + (size_t)c * 100 * 128;
    for (int idx = threadIdx.x; idx < 7 * 16 * 32; idx += 256) {
        int kk = idx >> 9, rem = idx & 511;
        int nt = rem >> 5, ln = rem & 31;
        int gg = ln >> 2, tt = ln & 3;
        int n = nt * 8 + gg, k0 = kk * 16 + 2 * tt;
        float v0 = (k0     < 100) ? w1[k0 * 128 + n]       : 0.0f;
        float v1 = (k0 + 1 < 100) ? w1[(k0 + 1) * 128 + n] : 0.0f;
        float v2 = (k0 + 8 < 100) ? w1[(k0 + 8) * 128 + n] : 0.0f;
        float v3 = (k0 + 9 < 100) ? w1[(k0 + 9) * 128 + n] : 0.0f;
        uint2 u; u.x = pack_h2(v0, v1); u.y = pack_h2(v2, v3);
        dst[idx] = u;
    }
    const float* w2 = W2 + (size_t)c * 128 * 64;
    for (int idx = threadIdx.x; idx < 8 * 8 * 32; idx += 256) {
        int kk = idx >> 8, rem = idx & 255;
        int nt = rem >> 5, ln = rem & 31;
        int gg = ln >> 2, tt = ln & 3;
        int n = nt * 8 + gg, k0 = kk * 16 + 2 * tt;
        uint2 u;
        u.x = pack_h2(w2[k0 * 64 + n],       w2[(k0 + 1) * 64 + n]);
        u.y = pack_h2(w2[(k0 + 8) * 64 + n], w2[(k0 + 9) * 64 + n]);
        dst[3584 + idx] = u;
    }
    const float* w3 = W3 + (size_t)c * 64 * 32;
    for (int idx = threadIdx.x; idx < 4 * 4 * 32; idx += 256) {
        int kk = idx >> 7, rem = idx & 127;
        int nt = rem >> 5, ln = rem & 31;
        int gg = ln >> 2, tt = ln & 3;
        int n = nt * 8 + gg, k0 = kk * 16 + 2 * tt;
        uint2 u;
        u.x = pack_h2(w3[k0 * 32 + n],       w3[(k0 + 1) * 32 + n]);
        u.y = pack_h2(w3[(k0 + 8) * 32 + n], w3[(k0 + 9) * 32 + n]);
        dst[5632 + idx] = u;
    }
}

__global__ __launch_bounds__(NT, 1) void mlp_mma_kernel(
    const float* __restrict__ b1, const float* __restrict__ b2,
    const float* __restrict__ b3, const float* __restrict__ W4,
    const float* __restrict__ b4, float* __restrict__ raw_out)
{
    extern __shared__ char smb[];
    float* b1s = (float*)(smb + OFF_B1);
    float* b2s = (float*)(smb + OFF_B2);
    float* b3s = (float*)(smb + OFF_B3);
    float* W4s = (float*)(smb + OFF_W4);

    const int bid   = blockIdx.x;
    const int c     = bid % NC;
    const int tbase = bid / NC;

    const int tid  = threadIdx.x;
    const int w    = tid >> 5;
    const int lane = tid & 31;
    const int g    = lane >> 2;
    const int tg   = lane & 3;
    const int G    = w >> 4;          // tile-group 0/1
    const int bs   = (w >> 2) & 3;    // big-stripe (32 rows)
    const int q    = w & 3;           // N quarter
    const int m0   = bs * 32;
    const int barid = 1 + G * 4 + bs;
    const int sg128 = tid & 127;

    uint32_t* A1g = (uint32_t*)(smb + OFF_A1) + G * (128 * SA1);
    uint32_t* H1g = (uint32_t*)(smb + OFF_H1) + G * (128 * SH1);
    float*    P4g = (float*)(smb + OFF_P) + G * 512;

    // ---- prologue: copy pre-permuted weights (L2-hot) + biases ----
    {
        const uint4* src = g_wpack + (size_t)c * 3072;
        uint4* dst = (uint4*)(smb + OFF_BW1);
        #pragma unroll
        for (int i = 0; i < 3; i++) dst[tid + i * NT] = src[tid + i * NT];
        if (tid < 128) b1s[tid] = b1[c * 128 + tid];
        if (tid < 64)  b2s[tid] = b2[c * 64 + tid];
        if (tid < 32)  b3s[tid] = b3[c * 32 + tid];
        if (tid < 32)  W4s[tid] = W4[c * 32 + tid];
    }
    const float b4c = b4[c];
    __syncthreads();

    const uint2* BW1 = (const uint2*)(smb + OFF_BW1);
    const uint2* BW2 = (const uint2*)(smb + OFF_BW2);

    // hoist L3 B fragments (constant): 4 kk, this warp's nt = q
    uint2 bw3[4];
    {
        const uint2* BW3 = (const uint2*)(smb + OFF_BW3);
        #pragma unroll
        for (int kk = 0; kk < 4; kk++) bw3[kk] = BW3[kk * 128 + q * 32 + lane];
    }

    const int h2b = m0 * SA1;   // H2 overlay base inside this group/stripe of A1

    // ldmatrix per-lane base addresses:
    // lanes 0-7: rows 0-7 (k lo), 8-15: rows 8-15 (k lo), 16-23: rows 0-7 (k hi), 24-31: rows 8-15 (k hi)
    const int lrow = lane & 15;
    const int lkof = (lane >> 2) & 4;   // +4 u32 for lanes 16..31
    const uint32_t aA1 = s_addr(A1g + (m0 + lrow) * SA1 + lkof);
    const uint32_t aH1 = s_addr(H1g + (m0 + lrow) * SH1 + lkof);
    const uint32_t aH2 = s_addr(A1g + h2b + lrow * SH2 + lkof);

    #pragma unroll
    for (int it = 0; it < 2; it++) {
        const int j = 2 * it + G;
        const size_t row0 = (size_t)(tbase + 256 * j) * TILE;

        // ---- load this big-stripe's 32 res rows (fp16, pad K to 120) ----
        {
            const uint32_t* rp = g_res_h2 + (row0 + m0) * 50;
            #pragma unroll
            for (int i = 0; i < 15; i++) {
                int idx = sg128 + i * 128;         // 0..1919
                int rr = idx / SA1, k2 = idx - rr * SA1;
                A1g[(m0 + rr) * SA1 + k2] = (k2 < 50) ? rp[rr * 50 + k2] : 0u;
            }
        }
        BAR_GRP(barid);

        // ============ L1: [32x112] @ W1 -> 32x32 (4 nt x 2 mh, 7 kk) ========
        float acc1[4][2][4];
        #pragma unroll
        for (int l = 0; l < 4; l++)
            #pragma unroll
            for (int mh = 0; mh < 2; mh++)
                #pragma unroll
                for (int p = 0; p < 4; p++) acc1[l][mh][p] = 0.0f;

        #pragma unroll
        for (int kk = 0; kk < 7; kk++) {
            uint32_t a[2][4];
            ldsm_x4(a[0], aA1 + kk * 32);
            ldsm_x4(a[1], aA1 + 16 * SA1 * 4 + kk * 32);
            const uint2* bp = BW1 + kk * 512 + (q * 4) * 32 + lane;
            #pragma unroll
            for (int l = 0; l < 4; l++) {
                uint2 b = bp[l * 32];
                mma_f16(acc1[l][0], a[0][0], a[0][1], a[0][2], a[0][3], b.x, b.y);
                mma_f16(acc1[l][1], a[1][0], a[1][1], a[1][2], a[1][3], b.x, b.y);
            }
        }
        #pragma unroll
        for (int l = 0; l < 4; l++) {
            int col = (q * 4 + l) * 8 + 2 * tg;
            float ba = b1s[col], bb = b1s[col + 1];
            int p2 = (q * 4 + l) * 4 + tg;
            #pragma unroll
            for (int mh = 0; mh < 2; mh++) {
                int rb = m0 + mh * 16;
                H1g[(rb + g) * SH1 + p2]     = silu2(acc1[l][mh][0] + ba, acc1[l][mh][1] + bb);
                H1g[(rb + g + 8) * SH1 + p2] = silu2(acc1[l][mh][2] + ba, acc1[l][mh][3] + bb);
            }
        }
        BAR_GRP(barid);

        // ============ L2: [32x128] @ W2 -> 32x16 (2 nt x 2 mh, 8 kk) ========
        float acc2[2][2][4];
        #pragma unroll
        for (int l = 0; l < 2; l++)
            #pragma unroll
            for (int mh = 0; mh < 2; mh++)
                #pragma unroll
                for (int p = 0; p < 4; p++) acc2[l][mh][p] = 0.0f;

        #pragma unroll
        for (int kk = 0; kk < 8; kk++) {
            uint32_t a[2][4];
            ldsm_x4(a[0], aH1 + kk * 32);
            ldsm_x4(a[1], aH1 + 16 * SH1 * 4 + kk * 32);
            const uint2* bp = BW2 + kk * 256 + (q * 2) * 32 + lane;
            #pragma unroll
            for (int l = 0; l < 2; l++) {
                uint2 b = bp[l * 32];
                mma_f16(acc2[l][0], a[0][0], a[0][1], a[0][2], a[0][3], b.x, b.y);
                mma_f16(acc2[l][1], a[1][0], a[1][1], a[1][2], a[1][3], b.x, b.y);
            }
        }
        #pragma unroll
        for (int l = 0; l < 2; l++) {
            int col = (q * 2 + l) * 8 + 2 * tg;
            float ba = b2s[col], bb = b2s[col + 1];
            int p2 = (q * 2 + l) * 4 + tg;
            #pragma unroll
            for (int mh = 0; mh < 2; mh++) {
                int r2 = mh * 16;
                A1g[h2b + (r2 + g) * SH2 + p2]     = silu2(acc2[l][mh][0] + ba, acc2[l][mh][1] + bb);
                A1g[h2b + (r2 + g + 8) * SH2 + p2] = silu2(acc2[l][mh][2] + ba, acc2[l][mh][3] + bb);
            }
        }
        BAR_GRP(barid);

        // ============ L3: [32x64] @ W3 -> 32x8 (1 nt x 2 mh, 4 kk) ==========
        float acc3[2][4];
        #pragma unroll
        for (int mh = 0; mh < 2; mh++)
            #pragma unroll
            for (int p = 0; p < 4; p++) acc3[mh][p] = 0.0f;

        #pragma unroll
        for (int kk = 0; kk < 4; kk++) {
            uint32_t a[2][4];
            ldsm_x4(a[0], aH2 + kk * 32);
            ldsm_x4(a[1], aH2 + 16 * SH2 * 4 + kk * 32);
            mma_f16(acc3[0], a[0][0], a[0][1], a[0][2], a[0][3], bw3[kk].x, bw3[kk].y);
            mma_f16(acc3[1], a[1][0], a[1][1], a[1][2], a[1][3], bw3[kk].x, bw3[kk].y);
        }

        // ---- epi3: partial dot over this warp's 8 cols (fp32 silu) ----
        {
            int col = q * 8 + 2 * tg;
            float ba = b3s[col], bb = b3s[col + 1];
            float wa = W4s[col], wb = W4s[col + 1];
            #pragma unroll
            for (int mh = 0; mh < 2; mh++) {
                float s0 = fmaf(silu(acc3[mh][0] + ba), wa, silu(acc3[mh][1] + bb) * wb);
                float s1 = fmaf(silu(acc3[mh][2] + ba), wa, silu(acc3[mh][3] + bb) * wb);
                s0 += __shfl_xor_sync(0xffffffff, s0, 1);
                s0 += __shfl_xor_sync(0xffffffff, s0, 2);
                s1 += __shfl_xor_sync(0xffffffff, s1, 1);
                s1 += __shfl_xor_sync(0xffffffff, s1, 2);
                if (tg == 0) {
                    P4g[(m0 + mh * 16 + g) * 4 + q]     = s0;
                    P4g[(m0 + mh * 16 + g + 8) * 4 + q] = s1;
                }
            }
        }
        BAR_GRP(barid);

        if (q == 0) {
            float4 p = *(float4*)&P4g[(m0 + lane) * 4];
            raw_out[(row0 + m0 + lane) * NC + c] = p.x + p.y + p.z + p.w + b4c;
        }
        BAR_GRP(barid);   // stripe drained; A1/P4 reusable next iteration
    }
}

__global__ __launch_bounds__(256) void couple_kernel(
    const float* __restrict__ raw, float* __restrict__ act,
    const float* __restrict__ coupling, const float* __restrict__ decay)
{
    __shared__ float M[NC][NC];
    if (threadIdx.x < NC * NC) {
        int cp = threadIdx.x / NC;
        int cc = threadIdx.x % NC;
        M[cp][cc] = decay[cp] * coupling[cp * NC + cc] * CF_K;
    }
    __syncthreads();

    int r = blockIdx.x * blockDim.x + threadIdx.x;
    if (r >= NB) return;

    float rw[NC], a[NC];
    const float2* rp = (const float2*)(raw + (size_t)r * NC);
    #pragma unroll
    for (int h = 0; h < 3; h++) {
        float2 v = rp[h];
        rw[2 * h] = v.x; rw[2 * h + 1] = v.y;
    }
    #pragma unroll
    for (int c = 0; c < NC; c++) a[c] = sigm(rw[c]);

    #pragma unroll
    for (int it = 0; it < 5; it++) {
        float d[NC];
        #pragma unroll
        for (int c = 0; c < NC; c++) d[c] = 0.0f;
        #pragma unroll
        for (int cp = 0; cp < NC; cp++)
            #pragma unroll
            for (int cc = 0; cc < NC; cc++)
                d[cc] = fmaf(a[cp], M[cp][cc], d[cc]);
        #pragma unroll
        for (int c = 0; c < NC; c++) a[c] = sigm(rw[c] + d[c]);
    }
    float2* ap = (float2*)(act + (size_t)r * NC);
    #pragma unroll
    for (int h = 0; h < 3; h++) {
        float2 v; v.x = a[2 * h]; v.y = a[2 * h + 1];
        ap[h] = v;
    }
}

extern "C" void kernel_launch(void* const* d_in, const int* in_sizes, int n_in,
                              void* d_out, int out_size)
{
    (void)in_sizes; (void)n_in; (void)out_size;
    const float* res      = (const float*)d_in[0];
    const float* W1       = (const float*)d_in[1];
    const float* b1       = (const float*)d_in[2];
    const float* W2       = (const float*)d_in[3];
    const float* b2       = (const float*)d_in[4];
    const float* W3       = (const float*)d_in[5];
    const float* b3       = (const float*)d_in[6];
    const float* W4       = (const float*)d_in[7];
    const float* b4       = (const float*)d_in[8];
    const float* coupling = (const float*)d_in[9];
    const float* decay    = (const float*)d_in[10];

    float* act = (float*)d_out;             // (B, 6)
    float* raw = act + (size_t)NB * NC;     // (B, 6)

    cudaFuncSetAttribute(mlp_mma_kernel, cudaFuncAttributeMaxDynamicSharedMemorySize, SMEM_BYTES);

    conv_kernel<<<NB * 25 / 512, 512>>>(res);
    wsetup_kernel<<<NC, 256>>>(W1, W2, W3);
    mlp_mma_kernel<<<GRID_X, NT, SMEM_BYTES>>>(b1, b2, b3, W4, b4, raw);
    couple_kernel<<<NB / 256, 256>>>(raw, act, coupling, decay);
}